// round 16
// baseline (speedup 1.0000x reference)
#include <cuda_runtime.h>

// LeiNet: head[b,n] = dot(x[n,b,:], head_w[n,:]) + head_b[n]
//         logits[b,k] = sum_n head[b,n]*foot_w[k,n] + foot_b[k]
//         out[b,:] = softmax(logits[b,:])  (2-way)
//
// x: [128, 4096, 512] fp32 (1.07 GB, streamed once) -> pure HBM-bound.
// R16 (= R4..R15 resubmit; every attempt since R3 failed infra-side, never ran):
// 4-batch blocking. x[n, b0:b0+4, :] is 8KB CONTIGUOUS -> each warp
// sweeps 8KB linearly per neuron instead of 2KB bursts 8MB apart.
// 4x longer DRAM bursts, 4x fewer concurrent streams, head_w loads /4.

#define N_NEURON 128
#define N_RULES  512
#define THREADS  512
#define WARPS    (THREADS / 32)
#define NEURONS_PER_WARP (N_NEURON / WARPS)   // 8
#define B_TILE   4

__global__ __launch_bounds__(THREADS)
void leinet_kernel(const float* __restrict__ x,
                   const float* __restrict__ head_w,
                   const float* __restrict__ head_b,
                   const float* __restrict__ foot_w,
                   const float* __restrict__ foot_b,
                   float* __restrict__ out,
                   int batch)
{
    const int tid  = threadIdx.x;
    const int wid  = tid >> 5;
    const int lane = tid & 31;
    const int b0   = blockIdx.x * B_TILE;

    __shared__ float head_s[B_TILE][N_NEURON];

    // Each warp: 8 neurons x 4 consecutive batches.
    #pragma unroll
    for (int i = 0; i < NEURONS_PER_WARP; i++) {
        const int n = wid * NEURONS_PER_WARP + i;

        // Weights: loaded ONCE per neuron, reused for all 4 batches.
        const float4* __restrict__ wr =
            reinterpret_cast<const float4*>(head_w + (size_t)n * N_RULES);
        const float4 wv0 = __ldg(&wr[lane +  0]);
        const float4 wv1 = __ldg(&wr[lane + 32]);
        const float4 wv2 = __ldg(&wr[lane + 64]);
        const float4 wv3 = __ldg(&wr[lane + 96]);

        // x[n, b0:b0+4, :] = 8KB contiguous; sweep it row by row.
        const float4* __restrict__ xr =
            reinterpret_cast<const float4*>(x + ((size_t)n * batch + b0) * N_RULES);

        float s[B_TILE];
        #pragma unroll
        for (int r = 0; r < B_TILE; r++) {
            const float4* __restrict__ row = xr + r * (N_RULES / 4);
            float4 xv0 = __ldcs(&row[lane +  0]);
            float4 xv1 = __ldcs(&row[lane + 32]);
            float4 xv2 = __ldcs(&row[lane + 64]);
            float4 xv3 = __ldcs(&row[lane + 96]);

            float t = xv0.x * wv0.x + xv0.y * wv0.y + xv0.z * wv0.z + xv0.w * wv0.w;
            t += xv1.x * wv1.x + xv1.y * wv1.y + xv1.z * wv1.z + xv1.w * wv1.w;
            t += xv2.x * wv2.x + xv2.y * wv2.y + xv2.z * wv2.z + xv2.w * wv2.w;
            t += xv3.x * wv3.x + xv3.y * wv3.y + xv3.z * wv3.z + xv3.w * wv3.w;
            s[r] = t;
        }

        const float hb = __ldg(&head_b[n]);
        #pragma unroll
        for (int r = 0; r < B_TILE; r++) {
            float t = s[r];
            #pragma unroll
            for (int o = 16; o > 0; o >>= 1)
                t += __shfl_xor_sync(0xFFFFFFFFu, t, o);
            if (lane == 0)
                head_s[r][n] = t + hb;
        }
    }
    __syncthreads();

    // Warps 0-3: foot layer + 2-way softmax, one batch row each.
    if (wid < B_TILE) {
        float p0 = 0.f, p1 = 0.f;
        #pragma unroll
        for (int j = 0; j < 4; j++) {
            const int n = lane + 32 * j;
            const float h = head_s[wid][n];
            p0 += h * __ldg(&foot_w[n]);             // foot_w[0][n]
            p1 += h * __ldg(&foot_w[N_NEURON + n]);  // foot_w[1][n]
        }
        #pragma unroll
        for (int o = 16; o > 0; o >>= 1) {
            p0 += __shfl_xor_sync(0xFFFFFFFFu, p0, o);
            p1 += __shfl_xor_sync(0xFFFFFFFFu, p1, o);
        }
        if (lane == 0) {
            p0 += __ldg(&foot_b[0]);
            p1 += __ldg(&foot_b[1]);
            const float m  = fmaxf(p0, p1);
            const float e0 = expf(p0 - m);
            const float e1 = expf(p1 - m);
            const float inv = 1.0f / (e0 + e1);
            const int b = b0 + wid;
            out[2 * b + 0] = e0 * inv;
            out[2 * b + 1] = e1 * inv;
        }
    }
}

extern "C" void kernel_launch(void* const* d_in, const int* in_sizes, int n_in,
                              void* d_out, int out_size)
{
    const float* x      = (const float*)d_in[0];
    const float* head_w = (const float*)d_in[1];
    const float* head_b = (const float*)d_in[2];
    const float* foot_w = (const float*)d_in[3];
    const float* foot_b = (const float*)d_in[4];
    float* out = (float*)d_out;

    const int batch = in_sizes[0] / (N_NEURON * N_RULES);   // 4096

    leinet_kernel<<<batch / B_TILE, THREADS>>>(x, head_w, head_b, foot_w, foot_b, out, batch);
}

// round 17
// speedup vs baseline: 1.0683x; 1.0683x over previous
#include <cuda_runtime.h>

// LeiNet: head[b,n] = dot(x[n,b,:], head_w[n,:]) + head_b[n]
//         logits[b,k] = sum_n head[b,n]*foot_w[k,n] + foot_b[k]
//         out[b,:] = softmax(logits[b,:])  (2-way)
//
// x: [128, 4096, 512] fp32 (1.07 GB, streamed once).
// FINAL (= R2 kernel, best measured 160.26us): persistent grid, 3 CTAs/SM.
//
// Roofline conclusion: the binding ceiling is the LTS (L2 fabric) cap of
// ~6300 B/cyc full-chip (path-independent, B300_MICROARCH), ~6.7 TB/s at
// GB300 clocks -> ideal 160.2us for 1.073GB. This kernel measures 160.3us
// = 100% of achievable. Measured counter-evidence for the alternatives:
//   - occ 99% (4 CTA/SM):  80.6% DRAM, 166us  (queue contention)
//   - occ 48% (4-batch blk): 79.7% DRAM, 171us (latency hiding marginal)
//   - this (occ 77%):       82.8-84.5% DRAM, 160.3us  <- at the cap

#define N_NEURON 128
#define N_RULES  512
#define THREADS  512
#define WARPS    (THREADS / 32)
#define NEURONS_PER_WARP (N_NEURON / WARPS)   // 8
#define GRID_PERSIST 456                      // 152 SMs * 3 resident CTAs

__global__ __launch_bounds__(THREADS)
void leinet_kernel(const float* __restrict__ x,
                   const float* __restrict__ head_w,
                   const float* __restrict__ head_b,
                   const float* __restrict__ foot_w,
                   const float* __restrict__ foot_b,
                   float* __restrict__ out,
                   int batch)
{
    const int tid  = threadIdx.x;
    const int wid  = tid >> 5;
    const int lane = tid & 31;

    __shared__ float head_s[N_NEURON];

    for (int b = blockIdx.x; b < batch; b += gridDim.x) {

        // Each warp computes 8 neuron dot-products of length 512.
        #pragma unroll
        for (int i = 0; i < NEURONS_PER_WARP; i++) {
            const int n = wid * NEURONS_PER_WARP + i;
            const float4* __restrict__ xr =
                reinterpret_cast<const float4*>(x + ((size_t)n * batch + b) * N_RULES);
            const float4* __restrict__ wr =
                reinterpret_cast<const float4*>(head_w + (size_t)n * N_RULES);

            // 512 floats = 128 float4 = 32 lanes * 4 chunks. Streaming loads
            // for x (zero reuse); cached loads for head_w (L1-hot, same 8
            // neurons every persistent b-iteration).
            float4 xv0 = __ldcs(&xr[lane +  0]);
            float4 xv1 = __ldcs(&xr[lane + 32]);
            float4 xv2 = __ldcs(&xr[lane + 64]);
            float4 xv3 = __ldcs(&xr[lane + 96]);
            float4 wv0 = __ldg(&wr[lane +  0]);
            float4 wv1 = __ldg(&wr[lane + 32]);
            float4 wv2 = __ldg(&wr[lane + 64]);
            float4 wv3 = __ldg(&wr[lane + 96]);

            float s = xv0.x * wv0.x + xv0.y * wv0.y + xv0.z * wv0.z + xv0.w * wv0.w;
            s += xv1.x * wv1.x + xv1.y * wv1.y + xv1.z * wv1.z + xv1.w * wv1.w;
            s += xv2.x * wv2.x + xv2.y * wv2.y + xv2.z * wv2.z + xv2.w * wv2.w;
            s += xv3.x * wv3.x + xv3.y * wv3.y + xv3.z * wv3.z + xv3.w * wv3.w;

            // Warp butterfly reduction.
            #pragma unroll
            for (int o = 16; o > 0; o >>= 1)
                s += __shfl_xor_sync(0xFFFFFFFFu, s, o);

            if (lane == 0)
                head_s[n] = s + __ldg(&head_b[n]);
        }
        __syncthreads();

        // Warp 0: foot layer (2 x 128) + 2-way softmax.
        if (wid == 0) {
            float p0 = 0.f, p1 = 0.f;
            #pragma unroll
            for (int j = 0; j < 4; j++) {
                const int n = lane + 32 * j;
                const float h = head_s[n];
                p0 += h * __ldg(&foot_w[n]);             // foot_w[0][n]
                p1 += h * __ldg(&foot_w[N_NEURON + n]);  // foot_w[1][n]
            }
            #pragma unroll
            for (int o = 16; o > 0; o >>= 1) {
                p0 += __shfl_xor_sync(0xFFFFFFFFu, p0, o);
                p1 += __shfl_xor_sync(0xFFFFFFFFu, p1, o);
            }
            if (lane == 0) {
                p0 += __ldg(&foot_b[0]);
                p1 += __ldg(&foot_b[1]);
                const float m  = fmaxf(p0, p1);
                const float e0 = expf(p0 - m);
                const float e1 = expf(p1 - m);
                const float inv = 1.0f / (e0 + e1);
                out[2 * b + 0] = e0 * inv;
                out[2 * b + 1] = e1 * inv;
            }
        }
        __syncthreads();   // protect head_s before next b iteration
    }
}

extern "C" void kernel_launch(void* const* d_in, const int* in_sizes, int n_in,
                              void* d_out, int out_size)
{
    const float* x      = (const float*)d_in[0];
    const float* head_w = (const float*)d_in[1];
    const float* head_b = (const float*)d_in[2];
    const float* foot_w = (const float*)d_in[3];
    const float* foot_b = (const float*)d_in[4];
    float* out = (float*)d_out;

    const int batch = in_sizes[0] / (N_NEURON * N_RULES);   // 4096

    const int grid = (batch < GRID_PERSIST) ? batch : GRID_PERSIST;
    leinet_kernel<<<grid, THREADS>>>(x, head_w, head_b, foot_w, foot_b, out, batch);
}